// round 1
// baseline (speedup 1.0000x reference)
#include <cuda_runtime.h>
#include <math.h>

// Global scratch for the max-abs reduction (monotone uint encoding of a
// non-negative float). Reset by a kernel each launch so the whole sequence is
// deterministic under graph replay.
__device__ unsigned int g_maxbits;

__global__ void bq_reset_kernel() {
    g_maxbits = 0u;
}

__global__ void bq_max_reduce_kernel(const float4* __restrict__ x, long long nvec,
                                     const float* __restrict__ xs, long long ntail_base,
                                     int ntail) {
    float m = 0.0f;
    long long stride = (long long)gridDim.x * blockDim.x;
    for (long long i = blockIdx.x * (long long)blockDim.x + threadIdx.x; i < nvec; i += stride) {
        float4 v = x[i];
        float a = fmaxf(fabsf(v.x), fabsf(v.y));
        float b = fmaxf(fabsf(v.z), fabsf(v.w));
        m = fmaxf(m, fmaxf(a, b));
    }
    // scalar tail (elements beyond the last full float4)
    if (blockIdx.x == 0 && threadIdx.x < (unsigned)ntail) {
        m = fmaxf(m, fabsf(xs[ntail_base + threadIdx.x]));
    }

    // warp reduce
    #pragma unroll
    for (int o = 16; o > 0; o >>= 1)
        m = fmaxf(m, __shfl_xor_sync(0xffffffffu, m, o));

    __shared__ float sm[32];
    int lane = threadIdx.x & 31;
    int w = threadIdx.x >> 5;
    if (lane == 0) sm[w] = m;
    __syncthreads();
    if (w == 0) {
        int nw = (blockDim.x + 31) >> 5;
        m = (lane < nw) ? sm[lane] : 0.0f;
        #pragma unroll
        for (int o = 16; o > 0; o >>= 1)
            m = fmaxf(m, __shfl_xor_sync(0xffffffffu, m, o));
        if (lane == 0)
            atomicMax(&g_maxbits, __float_as_uint(m));
    }
}

__device__ __forceinline__ float bq_quant_one(float v, float s, float inv_s) {
    // push magnitudes away from zero (zeros -> +1e-10), as in the reference
    v = (v >= 0.0f) ? fmaxf(v, 1e-10f) : fminf(v, -1e-10f);
    float i = rintf(v * s);                 // round half-to-even, matches jnp.round
    i = fminf(fmaxf(i, -128.0f), 127.0f);   // clip to [-2^7, 2^7-1]
    return i * inv_s;                        // exact: integer * power of two
}

__global__ void bq_quantize_kernel(const float4* __restrict__ x, float4* __restrict__ y,
                                   long long nvec,
                                   const float* __restrict__ xs, float* __restrict__ ys,
                                   long long ntail_base, int ntail) {
    // max entry after the 1e-10 clamp (the clamp can only raise tiny maxima)
    float maxv = fmaxf(__uint_as_float(g_maxbits), 1e-10f);
    // max_exponent = clip(floor(log2(max)), -128, 127); f32 log2 to mirror jnp
    float e = floorf(log2f(maxv));
    e = fminf(fmaxf(e, -128.0f), 127.0f);
    float s     = exp2f(-e + 6.0f);  // 2^(-e + (bits-2)), bits=8
    float inv_s = exp2f(e - 6.0f);

    long long stride = (long long)gridDim.x * blockDim.x;
    for (long long i = blockIdx.x * (long long)blockDim.x + threadIdx.x; i < nvec; i += stride) {
        float4 v = x[i];
        v.x = bq_quant_one(v.x, s, inv_s);
        v.y = bq_quant_one(v.y, s, inv_s);
        v.z = bq_quant_one(v.z, s, inv_s);
        v.w = bq_quant_one(v.w, s, inv_s);
        y[i] = v;
    }
    if (blockIdx.x == 0 && threadIdx.x < (unsigned)ntail) {
        ys[ntail_base + threadIdx.x] = bq_quant_one(xs[ntail_base + threadIdx.x], s, inv_s);
    }
}

extern "C" void kernel_launch(void* const* d_in, const int* in_sizes, int n_in,
                              void* d_out, int out_size) {
    const float* x = (const float*)d_in[0];
    float* y = (float*)d_out;
    long long n = (long long)in_sizes[0];
    long long nvec = n >> 2;                // full float4s
    long long ntail_base = nvec << 2;
    int ntail = (int)(n - ntail_base);

    bq_reset_kernel<<<1, 1>>>();

    const int THREADS = 256;
    // Reduce: enough CTAs to saturate HBM with grid-stride streaming.
    int red_blocks = 148 * 16;
    bq_max_reduce_kernel<<<red_blocks, THREADS>>>(
        (const float4*)x, nvec, x, ntail_base, ntail);

    // Quantize: streaming read+write.
    int q_blocks = 148 * 32;
    long long needed = (nvec + THREADS - 1) / THREADS;
    if ((long long)q_blocks > needed && needed > 0) q_blocks = (int)needed;
    if (q_blocks < 1) q_blocks = 1;
    bq_quantize_kernel<<<q_blocks, THREADS>>>(
        (const float4*)x, (float4*)y, nvec, x, y, ntail_base, ntail);
}